// round 6
// baseline (speedup 1.0000x reference)
#include <cuda_runtime.h>
#include <cstdint>

#define HH 512
#define WW 512
#define BATCH 16
#define WORDS 16   // u32 words per row
#define SWD 8      // u64 words per row
#define TILE 64
#define STH 68     // smem row stride (floats) for H/V/mag

// Scratch: bit-packed strong/weak masks (uint64-aligned).
__device__ uint64_t g_strong[2 * BATCH * HH * SWD];   // 1 MB
__device__ uint64_t g_weak[2 * BATCH * HH * SWD];     // 1 MB
__device__ int g_cnt;
__device__ int g_done;

__device__ __forceinline__ int reflect_idx(int p, int n) {
    if (p < 0) p = -p;
    if (p >= n) p = 2 * n - 2 - p;
    return p;
}

// ---------------- Kernel 1: (gray+hblur fused) -> vblur -> sobel+mag+bin -> NMS -> threshold -----
#define NT 256
__global__ __launch_bounds__(NT, 5) void canny_state_kernel(
    const float* __restrict__ in0, const float* __restrict__ in1)
{
    __shared__ float Hs[72 * STH];        // hblur, later mag
    __shared__ float Vs[68 * STH + 8];    // vblur (+pad for tail f4 over-read)
    __shared__ unsigned char bins[66 * STH];

    const int tx = blockIdx.x, ty = blockIdx.y, z = blockIdx.z;
    const int u = z >> 4, b = z & 15;
    const float* img = (u == 0 ? in0 : in1) + (size_t)b * 3 * HH * WW;
    const int TX = tx * TILE, TY = ty * TILE;
    const int tid = threadIdx.x;
    const int wid = tid >> 5, lane = tid & 31;

    if (z == 0 && tx == 0 && ty == 0 && tid == 0) { g_cnt = 0; g_done = 0; }

    // Gaussian weights (sigma=1, 5 taps) — same formula as reference
    const float e2 = expf(-2.0f), e05 = expf(-0.5f);
    const float ssum = (((e2 + e05) + 1.0f) + e05) + e2;
    const float w0 = e2 / ssum, w1 = e05 / ssum, w2 = 1.0f / ssum;

    // ---- Phase 1 (fused): grayscale in registers + horizontal blur -> Hs[72][68]
    // Row r covers global row reflect(TY-4+r); hblur col j (0..67) = gray cols j..j+4,
    // gray col g = global col TX-4+g. One warp per row; lane l owns gray f4 at cols 4l..4l+3.
    {
        const bool interior = (TX >= 4) && (TX + 68 <= WW);
        for (int r = wid; r < 72; r += NT / 32) {
            int rr = reflect_idx(TY - 4 + r, HH);
            const float* rowp = img + (size_t)rr * WW;
            float4 g = make_float4(0.f, 0.f, 0.f, 0.f);
            if (lane < 18) {
                if (interior) {
                    const float* p = rowp + (TX - 4) + 4 * lane;
                    float4 rv = *(const float4*)p;
                    float4 gv = *(const float4*)(p + HH * WW);
                    float4 bv = *(const float4*)(p + 2 * HH * WW);
                    g.x = 0.299f * rv.x + 0.587f * gv.x + 0.114f * bv.x;
                    g.y = 0.299f * rv.y + 0.587f * gv.y + 0.114f * bv.y;
                    g.z = 0.299f * rv.z + 0.587f * gv.z + 0.114f * bv.z;
                    g.w = 0.299f * rv.w + 0.587f * gv.w + 0.114f * bv.w;
                } else {
                    float gg[4];
                    #pragma unroll
                    for (int k = 0; k < 4; k++) {
                        int rc = reflect_idx(TX - 4 + 4 * lane + k, WW);
                        gg[k] = 0.299f * rowp[rc] + 0.587f * rowp[rc + HH * WW]
                              + 0.114f * rowp[rc + 2 * HH * WW];
                    }
                    g = make_float4(gg[0], gg[1], gg[2], gg[3]);
                }
            }
            float4 gn;
            gn.x = __shfl_down_sync(0xffffffffu, g.x, 1);
            gn.y = __shfl_down_sync(0xffffffffu, g.y, 1);
            gn.z = __shfl_down_sync(0xffffffffu, g.z, 1);
            gn.w = __shfl_down_sync(0xffffffffu, g.w, 1);
            if (lane < 17) {
                float4 o;
                o.x = w0 * (g.x + gn.x) + w1 * (g.y + g.w)  + w2 * g.z;
                o.y = w0 * (g.y + gn.y) + w1 * (g.z + gn.x) + w2 * g.w;
                o.z = w0 * (g.z + gn.z) + w1 * (g.w + gn.y) + w2 * gn.x;
                o.w = w0 * (g.w + gn.w) + w1 * (gn.x + gn.z) + w2 * gn.y;
                *(float4*)&Hs[r * STH + 4 * lane] = o;
            }
        }
    }
    __syncthreads();

    // ---- Phase 2: vertical 5-tap blur. Hs -> Vs[68][68], 2-row register blocks
    for (int t = tid; t < 34 * 17; t += NT) {
        int rg = t / 17, c4 = t % 17;
        float4 y[6];
        #pragma unroll
        for (int k = 0; k < 6; k++) y[k] = *(const float4*)&Hs[(2 * rg + k) * STH + 4 * c4];
        float4 o0, o1;
        o0.x = w0 * (y[0].x + y[4].x) + w1 * (y[1].x + y[3].x) + w2 * y[2].x;
        o0.y = w0 * (y[0].y + y[4].y) + w1 * (y[1].y + y[3].y) + w2 * y[2].y;
        o0.z = w0 * (y[0].z + y[4].z) + w1 * (y[1].z + y[3].z) + w2 * y[2].z;
        o0.w = w0 * (y[0].w + y[4].w) + w1 * (y[1].w + y[3].w) + w2 * y[2].w;
        o1.x = w0 * (y[1].x + y[5].x) + w1 * (y[2].x + y[4].x) + w2 * y[3].x;
        o1.y = w0 * (y[1].y + y[5].y) + w1 * (y[2].y + y[4].y) + w2 * y[3].y;
        o1.z = w0 * (y[1].z + y[5].z) + w1 * (y[2].z + y[4].z) + w2 * y[3].z;
        o1.w = w0 * (y[1].w + y[5].w) + w1 * (y[2].w + y[4].w) + w2 * y[3].w;
        *(float4*)&Vs[(2 * rg) * STH + 4 * c4] = o0;
        *(float4*)&Vs[(2 * rg + 1) * STH + 4 * c4] = o1;
    }
    __syncthreads();

    // ---- Phase 3: fused sobel + magnitude + direction bin. Vs -> Hs(mag rows 0..65), bins
    // mag[r][c] corresponds to global pixel (TY-1+r, TX-1+c), r,c in 0..65
    const float TAN22 = 0.41421356237309503f;  // tan(pi/8)
    for (int t = tid; t < 66 * 17; t += NT) {
        int r = t / 17, c4 = t % 17;
        float cs[3][4], cd[3][4];
        #pragma unroll
        for (int i = 0; i < 3; i++) {
            float4 xa = *(const float4*)&Vs[(r + i) * STH + 4 * c4];
            float4 xb = *(const float4*)&Vs[(r + i) * STH + 4 * c4 + 4];
            float x0 = xa.x, x1 = xa.y, x2 = xa.z, x3 = xa.w;
            float x4 = xb.x, x5 = xb.y, x6 = xb.z;
            cs[i][0] = x0 + 2.f * x1 + x2;  cd[i][0] = x2 - x0;
            cs[i][1] = x1 + 2.f * x2 + x3;  cd[i][1] = x3 - x1;
            cs[i][2] = x2 + 2.f * x3 + x4;  cd[i][2] = x4 - x2;
            cs[i][3] = x3 + 2.f * x4 + x5;  cd[i][3] = x5 - x3;
        }
        int gy_g = TY - 1 + r;
        bool row_ok = (gy_g >= 0) && (gy_g < HH);
        float m4[4]; uchar4 bo;
        #pragma unroll
        for (int jj = 0; jj < 4; jj++) {
            int c = 4 * c4 + jj;
            float gxv = cd[0][jj] + 2.f * cd[1][jj] + cd[2][jj];
            float gyv = cs[2][jj] - cs[0][jj];
            int gx_g = TX - 1 + c;
            float mag = 0.f;
            if (row_ok && gx_g >= 0 && gx_g < WW)
                mag = sqrtf(gxv * gxv + gyv * gyv + 1e-12f);
            m4[jj] = mag;
            float ax = fabsf(gxv), ay = fabsf(gyv);
            int bin;
            if (ay <= TAN22 * ax)      bin = 0;
            else if (ax <= TAN22 * ay) bin = 2;
            else bin = ((gxv > 0.f) == (gyv > 0.f)) ? 1 : 3;
            ((unsigned char*)&bo)[jj] = (unsigned char)bin;
        }
        *(float4*)&Hs[r * STH + 4 * c4] = make_float4(m4[0], m4[1], m4[2], m4[3]);
        *(uchar4*)&bins[r * STH + 4 * c4] = bo;
    }
    __syncthreads();

    // ---- Phase 4: NMS + double threshold, bit-pack via ballot (mag in Hs)
    uint32_t* gs32 = (uint32_t*)g_strong;
    uint32_t* gw32 = (uint32_t*)g_weak;
    for (int t = wid; t < 128; t += NT / 32) {   // 64 rows x 2 column-segments
        int r = t >> 1, seg = t & 1;
        int c = seg * 32 + lane;
        int mr = r + 1, mc = c + 1;
        int bin = bins[mr * STH + mc];
        int dy = (bin == 0) ? 0 : 1;
        int dx = (bin == 2) ? 0 : ((bin == 3) ? -1 : 1);
        float magc = Hs[mr * STH + mc];
        float n1 = Hs[(mr + dy) * STH + (mc + dx)];
        float n2 = Hs[(mr - dy) * STH + (mc - dx)];
        bool keep = (magc >= n1) && (magc >= n2);
        float nms = keep ? magc : 0.f;
        bool strong = (nms >= 0.2f);
        bool weak = (!strong) && (nms >= 0.1f);
        unsigned sm = __ballot_sync(0xffffffffu, strong);
        unsigned wm = __ballot_sync(0xffffffffu, weak);
        if (lane == 0) {
            size_t idx = (((size_t)(u * BATCH + b) * HH) + (TY + r)) * WORDS + (tx * 2 + seg);
            gs32[idx] = sm;
            gw32[idx] = wm;
        }
    }
}

// ---------------- Kernel 2: 10x hysteresis (uint64, full-width strips) + count + finalize ---------
#define SROWS 84    // 64 + 2*10 halo rows
#define SPITCH 10   // padded S row (1 u64 pad each side)

__global__ __launch_bounds__(448) void hyst_count_kernel(float* __restrict__ out)
{
    __shared__ uint64_t Ssh[2][SROWS][SPITCH];        // 13.4 KB
    __shared__ uint64_t Hsh[2][SROWS + 2][SWD];       // 11.0 KB
    __shared__ int warpsum[14];

    const int SY = blockIdx.x * 64;
    const int b = blockIdx.y;
    const int tid = threadIdx.x;

    // zero pads
    for (int i = tid; i < 2 * SROWS; i += 448) {
        int uu = i / SROWS, r = i % SROWS;
        Ssh[uu][r][0] = 0; Ssh[uu][r][SPITCH - 1] = 0;
    }
    if (tid < 2 * SWD) {
        int uu = tid / SWD, w = tid % SWD;
        Hsh[uu][0][w] = 0; Hsh[uu][SROWS + 1][w] = 0;
    }

    // 3 tasks per thread (1344 = 448*3), decomposed once
    int uu_[3], r_[3], w_[3];
    uint64_t s_[3], wk_[3], h_[3];
    uint64_t *pS[3], *pH[3];
    #pragma unroll
    for (int q = 0; q < 3; q++) {
        int t = tid + q * 448;
        int uu = t / 672, rem = t % 672;
        int r = rem >> 3, w = rem & 7;
        uu_[q] = uu; r_[q] = r; w_[q] = w;
        int gy = SY - 10 + r;
        uint64_t sv = 0, wv = 0;
        if (gy >= 0 && gy < HH) {
            size_t idx = (((size_t)(uu * BATCH + b)) * HH + gy) * SWD + w;
            sv = g_strong[idx];
            wv = g_weak[idx];
        }
        s_[q] = sv; wk_[q] = wv;
        pS[q] = &Ssh[uu][r][w + 1];
        pH[q] = &Hsh[uu][r + 1][w];
        *pS[q] = sv;
    }
    __syncthreads();

    for (int it = 0; it < 10; it++) {
        #pragma unroll
        for (int q = 0; q < 3; q++) {
            uint64_t s = s_[q];
            uint64_t lf = pS[q][-1], rt = pS[q][1];
            uint64_t h = s | (s << 1) | (s >> 1) | (lf >> 63) | (rt << 63);
            h_[q] = h;
            *pH[q] = h;
        }
        __syncthreads();
        #pragma unroll
        for (int q = 0; q < 3; q++) {
            uint64_t nb = h_[q] | pH[q][-SWD] | pH[q][SWD];
            uint64_t pr = wk_[q] & nb;
            s_[q] |= pr;
            wk_[q] &= ~pr;
            *pS[q] = s_[q];
        }
        __syncthreads();
    }

    // XOR-popcount over 64-row interior (r in 10..73)
    int cnt = 0;
    #pragma unroll
    for (int q = 0; q < 3; q++) {
        if (uu_[q] == 0 && r_[q] >= 10 && r_[q] < 74)
            cnt += __popcll(s_[q] ^ Ssh[1][r_[q]][w_[q] + 1]);
    }
    #pragma unroll
    for (int off = 16; off; off >>= 1)
        cnt += __shfl_down_sync(0xffffffffu, cnt, off);
    if ((tid & 31) == 0) warpsum[tid >> 5] = cnt;
    __syncthreads();
    if (tid == 0) {
        int tot = 0;
        #pragma unroll
        for (int k = 0; k < 14; k++) tot += warpsum[k];
        atomicAdd(&g_cnt, tot);
        __threadfence();
        int ticket = atomicAdd(&g_done, 1);
        if (ticket == 8 * BATCH - 1) {
            int total = atomicAdd(&g_cnt, 0);
            out[0] = (float)total / 4194304.0f;  // 16*512*512
        }
    }
}

extern "C" void kernel_launch(void* const* d_in, const int* in_sizes, int n_in,
                              void* d_out, int out_size) {
    const float* y_hat = (const float*)d_in[0];
    const float* y     = (const float*)d_in[1];
    float* out = (float*)d_out;

    dim3 g1(WW / TILE, HH / TILE, 2 * BATCH);   // 8 x 8 x 32
    canny_state_kernel<<<g1, NT>>>(y_hat, y);
    dim3 g2(HH / TILE, BATCH);                  // 8 x 16 strips
    hyst_count_kernel<<<g2, 448>>>(out);
}

// round 7
// speedup vs baseline: 1.4036x; 1.4036x over previous
#include <cuda_runtime.h>
#include <cstdint>

#define HH 512
#define WW 512
#define BATCH 16
#define WORDS 16   // u32 words per row
#define SWD 8      // u64 words per row
#define TILE 64
#define STH 68     // smem row stride (floats)

// Scratch: bit-packed strong/weak masks (uint64-aligned).
__device__ uint64_t g_strong[2 * BATCH * HH * SWD];   // 1 MB
__device__ uint64_t g_weak[2 * BATCH * HH * SWD];     // 1 MB
__device__ int g_cnt;
__device__ int g_done;

__device__ __forceinline__ int reflect_idx(int p, int n) {
    if (p < 0) p = -p;
    if (p >= n) p = 2 * n - 2 - p;
    return p;
}

// ---------------- Kernel 1: (gray+hblur per-thread) -> vblur -> sobel+mag+bin -> NMS ----------
#define NT 256
__global__ __launch_bounds__(NT, 5) void canny_state_kernel(
    const float* __restrict__ in0, const float* __restrict__ in1)
{
    __shared__ float Hs[72 * STH];          // hblur, later mag
    __shared__ float Vs[68 * STH + 8];      // vblur (+pad for tail f4 over-read)
    __shared__ unsigned char binp[66 * 17]; // 2-bit packed direction bins, 4 pixels/byte

    const int tx = blockIdx.x, ty = blockIdx.y, z = blockIdx.z;
    const int u = z >> 4, b = z & 15;
    const float* img = (u == 0 ? in0 : in1) + (size_t)b * 3 * HH * WW;
    const int TX = tx * TILE, TY = ty * TILE;
    const int tid = threadIdx.x;

    if (z == 0 && tx == 0 && ty == 0 && tid == 0) { g_cnt = 0; g_done = 0; }

    // Gaussian weights (sigma=1, 5 taps) — same formula as reference
    const float e2 = expf(-2.0f), e05 = expf(-0.5f);
    const float ssum = (((e2 + e05) + 1.0f) + e05) + e2;
    const float w0 = e2 / ssum, w1 = e05 / ssum, w2 = 1.0f / ssum;

    // ---- Phase 1 (fused, per-thread): grayscale in registers + horizontal blur -> Hs[72][68]
    // Task (r, c4): hblur cols 4c4..4c4+3 of row r need gray cols 4c4..4c4+7
    // (gray col g <-> global col TX-4+g; row r <-> global row reflect(TY-4+r)).
    {
        const bool interior = (TX >= 4) && (TX + 68 <= WW);
        const int HW = HH * WW;
        for (int t = tid; t < 72 * 17; t += NT) {
            int r = t / 17, c4 = t % 17;
            int rr = reflect_idx(TY - 4 + r, HH);
            const float* rowp = img + (size_t)rr * WW;
            float g[8];
            if (interior) {
                const float* p = rowp + (TX - 4) + 4 * c4;
                float4 ra = *(const float4*)p,            rb = *(const float4*)(p + 4);
                float4 ga = *(const float4*)(p + HW),     gb = *(const float4*)(p + HW + 4);
                float4 ba = *(const float4*)(p + 2 * HW), bb = *(const float4*)(p + 2 * HW + 4);
                g[0] = 0.299f * ra.x + 0.587f * ga.x + 0.114f * ba.x;
                g[1] = 0.299f * ra.y + 0.587f * ga.y + 0.114f * ba.y;
                g[2] = 0.299f * ra.z + 0.587f * ga.z + 0.114f * ba.z;
                g[3] = 0.299f * ra.w + 0.587f * ga.w + 0.114f * ba.w;
                g[4] = 0.299f * rb.x + 0.587f * gb.x + 0.114f * bb.x;
                g[5] = 0.299f * rb.y + 0.587f * gb.y + 0.114f * bb.y;
                g[6] = 0.299f * rb.z + 0.587f * gb.z + 0.114f * bb.z;
                g[7] = 0.299f * rb.w + 0.587f * gb.w + 0.114f * bb.w;
            } else {
                #pragma unroll
                for (int k = 0; k < 8; k++) {
                    int rc = reflect_idx(TX - 4 + 4 * c4 + k, WW);
                    g[k] = 0.299f * rowp[rc] + 0.587f * rowp[rc + HW] + 0.114f * rowp[rc + 2 * HW];
                }
            }
            float4 o;
            o.x = w0 * (g[0] + g[4]) + w1 * (g[1] + g[3]) + w2 * g[2];
            o.y = w0 * (g[1] + g[5]) + w1 * (g[2] + g[4]) + w2 * g[3];
            o.z = w0 * (g[2] + g[6]) + w1 * (g[3] + g[5]) + w2 * g[4];
            o.w = w0 * (g[3] + g[7]) + w1 * (g[4] + g[6]) + w2 * g[5];
            *(float4*)&Hs[r * STH + 4 * c4] = o;
        }
    }
    __syncthreads();

    // ---- Phase 2: vertical 5-tap blur. Hs -> Vs[68][68], 4-row register blocks
    for (int t = tid; t < 17 * 17; t += NT) {
        int rg = t / 17, c4 = t % 17;
        float4 y[8];
        #pragma unroll
        for (int k = 0; k < 8; k++) y[k] = *(const float4*)&Hs[(4 * rg + k) * STH + 4 * c4];
        #pragma unroll
        for (int j = 0; j < 4; j++) {
            float4 o;
            o.x = w0 * (y[j].x + y[j + 4].x) + w1 * (y[j + 1].x + y[j + 3].x) + w2 * y[j + 2].x;
            o.y = w0 * (y[j].y + y[j + 4].y) + w1 * (y[j + 1].y + y[j + 3].y) + w2 * y[j + 2].y;
            o.z = w0 * (y[j].z + y[j + 4].z) + w1 * (y[j + 1].z + y[j + 3].z) + w2 * y[j + 2].z;
            o.w = w0 * (y[j].w + y[j + 4].w) + w1 * (y[j + 1].w + y[j + 3].w) + w2 * y[j + 2].w;
            *(float4*)&Vs[(4 * rg + j) * STH + 4 * c4] = o;
        }
    }
    __syncthreads();

    // ---- Phase 3: fused sobel + magnitude + direction bin. Vs -> Hs(mag), binp
    // mag[r][c] corresponds to global pixel (TY-1+r, TX-1+c); valid r,c in 0..65
    const float TAN22 = 0.41421356237309503f;  // tan(pi/8)
    for (int t = tid; t < 66 * 17; t += NT) {
        int r = t / 17, c4 = t % 17;
        float cs[3][4], cd[3][4];
        #pragma unroll
        for (int i = 0; i < 3; i++) {
            float4 xa = *(const float4*)&Vs[(r + i) * STH + 4 * c4];
            float4 xb = *(const float4*)&Vs[(r + i) * STH + 4 * c4 + 4];
            float x0 = xa.x, x1 = xa.y, x2 = xa.z, x3 = xa.w;
            float x4 = xb.x, x5 = xb.y, x6 = xb.z;
            cs[i][0] = x0 + 2.f * x1 + x2;  cd[i][0] = x2 - x0;
            cs[i][1] = x1 + 2.f * x2 + x3;  cd[i][1] = x3 - x1;
            cs[i][2] = x2 + 2.f * x3 + x4;  cd[i][2] = x4 - x2;
            cs[i][3] = x3 + 2.f * x4 + x5;  cd[i][3] = x5 - x3;
        }
        int gy_g = TY - 1 + r;
        bool row_ok = (gy_g >= 0) && (gy_g < HH);
        float m4[4];
        unsigned pk = 0;
        #pragma unroll
        for (int jj = 0; jj < 4; jj++) {
            int c = 4 * c4 + jj;
            float gxv = cd[0][jj] + 2.f * cd[1][jj] + cd[2][jj];
            float gyv = cs[2][jj] - cs[0][jj];
            int gx_g = TX - 1 + c;
            float mag = 0.f;
            if (row_ok && gx_g >= 0 && gx_g < WW)
                mag = sqrtf(gxv * gxv + gyv * gyv + 1e-12f);
            m4[jj] = mag;
            float ax = fabsf(gxv), ay = fabsf(gyv);
            int bin;
            if (ay <= TAN22 * ax)      bin = 0;
            else if (ax <= TAN22 * ay) bin = 2;
            else bin = ((gxv > 0.f) == (gyv > 0.f)) ? 1 : 3;
            pk |= (unsigned)bin << (jj * 2);
        }
        *(float4*)&Hs[r * STH + 4 * c4] = make_float4(m4[0], m4[1], m4[2], m4[3]);
        binp[r * 17 + c4] = (unsigned char)pk;
    }
    __syncthreads();

    // ---- Phase 4: NMS + double threshold, bit-pack via ballot (mag in Hs)
    const int wid = tid >> 5, lane = tid & 31;
    uint32_t* gs32 = (uint32_t*)g_strong;
    uint32_t* gw32 = (uint32_t*)g_weak;
    for (int t = wid; t < 128; t += NT / 32) {   // 64 rows x 2 column-segments
        int r = t >> 1, seg = t & 1;
        int c = seg * 32 + lane;
        int mr = r + 1, mc = c + 1;
        int bin = (binp[mr * 17 + (mc >> 2)] >> ((mc & 3) * 2)) & 3;
        int dy = (bin == 0) ? 0 : 1;
        int dx = (bin == 2) ? 0 : ((bin == 3) ? -1 : 1);
        float magc = Hs[mr * STH + mc];
        float n1 = Hs[(mr + dy) * STH + (mc + dx)];
        float n2 = Hs[(mr - dy) * STH + (mc - dx)];
        bool keep = (magc >= n1) && (magc >= n2);
        float nms = keep ? magc : 0.f;
        bool strong = (nms >= 0.2f);
        bool weak = (!strong) && (nms >= 0.1f);
        unsigned sm = __ballot_sync(0xffffffffu, strong);
        unsigned wm = __ballot_sync(0xffffffffu, weak);
        if (lane == 0) {
            size_t idx = (((size_t)(u * BATCH + b) * HH) + (TY + r)) * WORDS + (tx * 2 + seg);
            gs32[idx] = sm;
            gw32[idx] = wm;
        }
    }
}

// ---------------- Kernel 2: 10x hysteresis (uint64, full-width strips) + count + finalize ---------
#define SROWS 84    // 64 + 2*10 halo rows
#define SPITCH 10   // padded S row (1 u64 pad each side)

__global__ __launch_bounds__(448) void hyst_count_kernel(float* __restrict__ out)
{
    __shared__ uint64_t Ssh[2][SROWS][SPITCH];        // 13.4 KB
    __shared__ uint64_t Hsh[2][SROWS + 2][SWD];       // 11.0 KB
    __shared__ int warpsum[14];

    const int SY = blockIdx.x * 64;
    const int b = blockIdx.y;
    const int tid = threadIdx.x;

    // zero pads
    for (int i = tid; i < 2 * SROWS; i += 448) {
        int uu = i / SROWS, r = i % SROWS;
        Ssh[uu][r][0] = 0; Ssh[uu][r][SPITCH - 1] = 0;
    }
    if (tid < 2 * SWD) {
        int uu = tid / SWD, w = tid % SWD;
        Hsh[uu][0][w] = 0; Hsh[uu][SROWS + 1][w] = 0;
    }

    // 3 tasks per thread (1344 = 448*3), decomposed once
    int uu_[3], r_[3], w_[3];
    uint64_t s_[3], wk_[3], h_[3];
    uint64_t *pS[3], *pH[3];
    #pragma unroll
    for (int q = 0; q < 3; q++) {
        int t = tid + q * 448;
        int uu = t / 672, rem = t % 672;
        int r = rem >> 3, w = rem & 7;
        uu_[q] = uu; r_[q] = r; w_[q] = w;
        int gy = SY - 10 + r;
        uint64_t sv = 0, wv = 0;
        if (gy >= 0 && gy < HH) {
            size_t idx = (((size_t)(uu * BATCH + b)) * HH + gy) * SWD + w;
            sv = g_strong[idx];
            wv = g_weak[idx];
        }
        s_[q] = sv; wk_[q] = wv;
        pS[q] = &Ssh[uu][r][w + 1];
        pH[q] = &Hsh[uu][r + 1][w];
        *pS[q] = sv;
    }
    __syncthreads();

    for (int it = 0; it < 10; it++) {
        #pragma unroll
        for (int q = 0; q < 3; q++) {
            uint64_t s = s_[q];
            uint64_t lf = pS[q][-1], rt = pS[q][1];
            uint64_t h = s | (s << 1) | (s >> 1) | (lf >> 63) | (rt << 63);
            h_[q] = h;
            *pH[q] = h;
        }
        __syncthreads();
        #pragma unroll
        for (int q = 0; q < 3; q++) {
            uint64_t nb = h_[q] | pH[q][-SWD] | pH[q][SWD];
            uint64_t pr = wk_[q] & nb;
            s_[q] |= pr;
            wk_[q] &= ~pr;
            *pS[q] = s_[q];
        }
        __syncthreads();
    }

    // XOR-popcount over 64-row interior (r in 10..73)
    int cnt = 0;
    #pragma unroll
    for (int q = 0; q < 3; q++) {
        if (uu_[q] == 0 && r_[q] >= 10 && r_[q] < 74)
            cnt += __popcll(s_[q] ^ Ssh[1][r_[q]][w_[q] + 1]);
    }
    #pragma unroll
    for (int off = 16; off; off >>= 1)
        cnt += __shfl_down_sync(0xffffffffu, cnt, off);
    if ((tid & 31) == 0) warpsum[tid >> 5] = cnt;
    __syncthreads();
    if (tid == 0) {
        int tot = 0;
        #pragma unroll
        for (int k = 0; k < 14; k++) tot += warpsum[k];
        atomicAdd(&g_cnt, tot);
        __threadfence();
        int ticket = atomicAdd(&g_done, 1);
        if (ticket == 8 * BATCH - 1) {
            int total = atomicAdd(&g_cnt, 0);
            out[0] = (float)total / 4194304.0f;  // 16*512*512
        }
    }
}

extern "C" void kernel_launch(void* const* d_in, const int* in_sizes, int n_in,
                              void* d_out, int out_size) {
    const float* y_hat = (const float*)d_in[0];
    const float* y     = (const float*)d_in[1];
    float* out = (float*)d_out;

    dim3 g1(WW / TILE, HH / TILE, 2 * BATCH);   // 8 x 8 x 32
    canny_state_kernel<<<g1, NT>>>(y_hat, y);
    dim3 g2(HH / TILE, BATCH);                  // 8 x 16 strips
    hyst_count_kernel<<<g2, 448>>>(out);
}

// round 11
// speedup vs baseline: 1.4403x; 1.0261x over previous
#include <cuda_runtime.h>
#include <cstdint>

#define HH 512
#define WW 512
#define BATCH 16
#define WORDS 16   // u32 words per row
#define SWD 8      // u64 words per row
#define TILE 64
#define STH 68     // smem row stride (floats)

// Scratch: bit-packed strong/weak masks (uint64-aligned).
__device__ uint64_t g_strong[2 * BATCH * HH * SWD];   // 1 MB
__device__ uint64_t g_weak[2 * BATCH * HH * SWD];     // 1 MB
__device__ int g_cnt;
__device__ int g_done;

__device__ __forceinline__ int reflect_idx(int p, int n) {
    if (p < 0) p = -p;
    if (p >= n) p = 2 * n - 2 - p;
    return p;
}

// ---------------- Kernel 1: (gray+hblur per-thread) -> vblur -> sobel+sq+bin -> NMS ----------
// NOTE: works with SQUARED magnitudes throughout. sqrt is monotone, so all NMS
// comparisons are decision-identical; thresholds use the exact preimages:
//   sqrt_rn(sq) >= 0.2f  <=>  sq >= 0.04f   (verified rounding boundary)
//   sqrt_rn(sq) >= 0.1f  <=>  sq >= 0.01f   (verified rounding boundary)
#define NT 256
__global__ __launch_bounds__(NT, 5) void canny_state_kernel(
    const float* __restrict__ in0, const float* __restrict__ in1)
{
    __shared__ float Hs[72 * STH];          // hblur, later sq-mag
    __shared__ float Vs[68 * STH + 8];      // vblur (+pad for tail f4 over-read)
    __shared__ unsigned char binp[66 * 17]; // 2-bit packed direction bins, 4 pixels/byte

    const int tx = blockIdx.x, ty = blockIdx.y, z = blockIdx.z;
    const int u = z >> 4, b = z & 15;
    const float* img = (u == 0 ? in0 : in1) + (size_t)b * 3 * HH * WW;
    const int TX = tx * TILE, TY = ty * TILE;
    const int tid = threadIdx.x;

    if (z == 0 && tx == 0 && ty == 0 && tid == 0) { g_cnt = 0; g_done = 0; }

    // Gaussian weights (sigma=1, 5 taps) — same formula as reference
    const float e2 = expf(-2.0f), e05 = expf(-0.5f);
    const float ssum = (((e2 + e05) + 1.0f) + e05) + e2;
    const float w0 = e2 / ssum, w1 = e05 / ssum, w2 = 1.0f / ssum;

    // ---- Phase 1 (fused, per-thread): grayscale in registers + horizontal blur -> Hs[72][68]
    {
        const bool interior = (TX >= 4) && (TX + 68 <= WW);
        const int HW = HH * WW;
        for (int t = tid; t < 72 * 17; t += NT) {
            int r = t / 17, c4 = t % 17;
            int rr = reflect_idx(TY - 4 + r, HH);
            const float* rowp = img + (size_t)rr * WW;
            float g[8];
            if (interior) {
                const float* p = rowp + (TX - 4) + 4 * c4;
                float4 ra = *(const float4*)p,            rb = *(const float4*)(p + 4);
                float4 ga = *(const float4*)(p + HW),     gb = *(const float4*)(p + HW + 4);
                float4 ba = *(const float4*)(p + 2 * HW), bb = *(const float4*)(p + 2 * HW + 4);
                g[0] = 0.299f * ra.x + 0.587f * ga.x + 0.114f * ba.x;
                g[1] = 0.299f * ra.y + 0.587f * ga.y + 0.114f * ba.y;
                g[2] = 0.299f * ra.z + 0.587f * ga.z + 0.114f * ba.z;
                g[3] = 0.299f * ra.w + 0.587f * ga.w + 0.114f * ba.w;
                g[4] = 0.299f * rb.x + 0.587f * gb.x + 0.114f * bb.x;
                g[5] = 0.299f * rb.y + 0.587f * gb.y + 0.114f * bb.y;
                g[6] = 0.299f * rb.z + 0.587f * gb.z + 0.114f * bb.z;
                g[7] = 0.299f * rb.w + 0.587f * gb.w + 0.114f * bb.w;
            } else {
                #pragma unroll
                for (int k = 0; k < 8; k++) {
                    int rc = reflect_idx(TX - 4 + 4 * c4 + k, WW);
                    g[k] = 0.299f * rowp[rc] + 0.587f * rowp[rc + HW] + 0.114f * rowp[rc + 2 * HW];
                }
            }
            float4 o;
            o.x = w0 * (g[0] + g[4]) + w1 * (g[1] + g[3]) + w2 * g[2];
            o.y = w0 * (g[1] + g[5]) + w1 * (g[2] + g[4]) + w2 * g[3];
            o.z = w0 * (g[2] + g[6]) + w1 * (g[3] + g[5]) + w2 * g[4];
            o.w = w0 * (g[3] + g[7]) + w1 * (g[4] + g[6]) + w2 * g[5];
            *(float4*)&Hs[r * STH + 4 * c4] = o;
        }
    }
    __syncthreads();

    // ---- Phase 2: vertical 5-tap blur. Hs -> Vs[68][68], 4-row register blocks
    for (int t = tid; t < 17 * 17; t += NT) {
        int rg = t / 17, c4 = t % 17;
        float4 y[8];
        #pragma unroll
        for (int k = 0; k < 8; k++) y[k] = *(const float4*)&Hs[(4 * rg + k) * STH + 4 * c4];
        #pragma unroll
        for (int j = 0; j < 4; j++) {
            float4 o;
            o.x = w0 * (y[j].x + y[j + 4].x) + w1 * (y[j + 1].x + y[j + 3].x) + w2 * y[j + 2].x;
            o.y = w0 * (y[j].y + y[j + 4].y) + w1 * (y[j + 1].y + y[j + 3].y) + w2 * y[j + 2].y;
            o.z = w0 * (y[j].z + y[j + 4].z) + w1 * (y[j + 1].z + y[j + 3].z) + w2 * y[j + 2].z;
            o.w = w0 * (y[j].w + y[j + 4].w) + w1 * (y[j + 1].w + y[j + 3].w) + w2 * y[j + 2].w;
            *(float4*)&Vs[(4 * rg + j) * STH + 4 * c4] = o;
        }
    }
    __syncthreads();

    // ---- Phase 3: fused sobel + SQUARED magnitude + direction bin. Vs -> Hs(sq), binp
    // sq[r][c] corresponds to global pixel (TY-1+r, TX-1+c); valid r,c in 0..65
    const float TAN22 = 0.41421356237309503f;  // tan(pi/8)
    for (int t = tid; t < 66 * 17; t += NT) {
        int r = t / 17, c4 = t % 17;
        float cs[3][4], cd[3][4];
        #pragma unroll
        for (int i = 0; i < 3; i++) {
            float4 xa = *(const float4*)&Vs[(r + i) * STH + 4 * c4];
            float4 xb = *(const float4*)&Vs[(r + i) * STH + 4 * c4 + 4];
            float x0 = xa.x, x1 = xa.y, x2 = xa.z, x3 = xa.w;
            float x4 = xb.x, x5 = xb.y, x6 = xb.z;
            cs[i][0] = x0 + 2.f * x1 + x2;  cd[i][0] = x2 - x0;
            cs[i][1] = x1 + 2.f * x2 + x3;  cd[i][1] = x3 - x1;
            cs[i][2] = x2 + 2.f * x3 + x4;  cd[i][2] = x4 - x2;
            cs[i][3] = x3 + 2.f * x4 + x5;  cd[i][3] = x5 - x3;
        }
        int gy_g = TY - 1 + r;
        bool row_ok = (gy_g >= 0) && (gy_g < HH);
        float m4[4];
        unsigned pk = 0;
        #pragma unroll
        for (int jj = 0; jj < 4; jj++) {
            int c = 4 * c4 + jj;
            float gxv = cd[0][jj] + 2.f * cd[1][jj] + cd[2][jj];
            float gyv = cs[2][jj] - cs[0][jj];
            int gx_g = TX - 1 + c;
            float sq = 0.f;
            if (row_ok && gx_g >= 0 && gx_g < WW)
                sq = gxv * gxv + gyv * gyv + 1e-12f;
            m4[jj] = sq;
            float ax = fabsf(gxv), ay = fabsf(gyv);
            int bin;
            if (ay <= TAN22 * ax)      bin = 0;
            else if (ax <= TAN22 * ay) bin = 2;
            else bin = ((gxv > 0.f) == (gyv > 0.f)) ? 1 : 3;
            pk |= (unsigned)bin << (jj * 2);
        }
        *(float4*)&Hs[r * STH + 4 * c4] = make_float4(m4[0], m4[1], m4[2], m4[3]);
        binp[r * 17 + c4] = (unsigned char)pk;
    }
    __syncthreads();

    // ---- Phase 4: NMS + double threshold on squared values, bit-pack via ballot
    const int wid = tid >> 5, lane = tid & 31;
    uint32_t* gs32 = (uint32_t*)g_strong;
    uint32_t* gw32 = (uint32_t*)g_weak;
    for (int t = wid; t < 128; t += NT / 32) {   // 64 rows x 2 column-segments
        int r = t >> 1, seg = t & 1;
        int c = seg * 32 + lane;
        int mr = r + 1, mc = c + 1;
        int bin = (binp[mr * 17 + (mc >> 2)] >> ((mc & 3) * 2)) & 3;
        int dy = (bin == 0) ? 0 : 1;
        int dx = (bin == 2) ? 0 : ((bin == 3) ? -1 : 1);
        float sqc = Hs[mr * STH + mc];
        float n1 = Hs[(mr + dy) * STH + (mc + dx)];
        float n2 = Hs[(mr - dy) * STH + (mc - dx)];
        bool keep = (sqc >= n1) && (sqc >= n2);
        float nms = keep ? sqc : 0.f;
        bool strong = (nms >= 0.04f);                    // == sqrt(nms) >= 0.2f (exact)
        bool weak = (!strong) && (nms >= 0.01f);         // == sqrt(nms) >= 0.1f (exact)
        unsigned sm = __ballot_sync(0xffffffffu, strong);
        unsigned wm = __ballot_sync(0xffffffffu, weak);
        if (lane == 0) {
            size_t idx = (((size_t)(u * BATCH + b) * HH) + (TY + r)) * WORDS + (tx * 2 + seg);
            gs32[idx] = sm;
            gw32[idx] = wm;
        }
    }
}

// ---------------- Kernel 2: 10x hysteresis (uint64, full-width strips) + count + finalize ---------
#define SROWS 84    // 64 + 2*10 halo rows
#define SPITCH 10   // padded S row (1 u64 pad each side)

__global__ __launch_bounds__(448) void hyst_count_kernel(float* __restrict__ out)
{
    __shared__ uint64_t Ssh[2][SROWS][SPITCH];        // 13.4 KB
    __shared__ uint64_t Hsh[2][SROWS + 2][SWD];       // 11.0 KB
    __shared__ int warpsum[14];

    const int SY = blockIdx.x * 64;
    const int b = blockIdx.y;
    const int tid = threadIdx.x;

    // zero pads
    for (int i = tid; i < 2 * SROWS; i += 448) {
        int uu = i / SROWS, r = i % SROWS;
        Ssh[uu][r][0] = 0; Ssh[uu][r][SPITCH - 1] = 0;
    }
    if (tid < 2 * SWD) {
        int uu = tid / SWD, w = tid % SWD;
        Hsh[uu][0][w] = 0; Hsh[uu][SROWS + 1][w] = 0;
    }

    // 3 tasks per thread (1344 = 448*3), decomposed once
    int uu_[3], r_[3], w_[3];
    uint64_t s_[3], wk_[3], h_[3];
    uint64_t *pS[3], *pH[3];
    #pragma unroll
    for (int q = 0; q < 3; q++) {
        int t = tid + q * 448;
        int uu = t / 672, rem = t % 672;
        int r = rem >> 3, w = rem & 7;
        uu_[q] = uu; r_[q] = r; w_[q] = w;
        int gy = SY - 10 + r;
        uint64_t sv = 0, wv = 0;
        if (gy >= 0 && gy < HH) {
            size_t idx = (((size_t)(uu * BATCH + b)) * HH + gy) * SWD + w;
            sv = g_strong[idx];
            wv = g_weak[idx];
        }
        s_[q] = sv; wk_[q] = wv;
        pS[q] = &Ssh[uu][r][w + 1];
        pH[q] = &Hsh[uu][r + 1][w];
        *pS[q] = sv;
    }
    __syncthreads();

    for (int it = 0; it < 10; it++) {
        #pragma unroll
        for (int q = 0; q < 3; q++) {
            uint64_t s = s_[q];
            uint64_t lf = pS[q][-1], rt = pS[q][1];
            uint64_t h = s | (s << 1) | (s >> 1) | (lf >> 63) | (rt << 63);
            h_[q] = h;
            *pH[q] = h;
        }
        __syncthreads();
        #pragma unroll
        for (int q = 0; q < 3; q++) {
            uint64_t nb = h_[q] | pH[q][-SWD] | pH[q][SWD];
            uint64_t pr = wk_[q] & nb;
            s_[q] |= pr;
            wk_[q] &= ~pr;
            *pS[q] = s_[q];
        }
        __syncthreads();
    }

    // XOR-popcount over 64-row interior (r in 10..73)
    int cnt = 0;
    #pragma unroll
    for (int q = 0; q < 3; q++) {
        if (uu_[q] == 0 && r_[q] >= 10 && r_[q] < 74)
            cnt += __popcll(s_[q] ^ Ssh[1][r_[q]][w_[q] + 1]);
    }
    #pragma unroll
    for (int off = 16; off; off >>= 1)
        cnt += __shfl_down_sync(0xffffffffu, cnt, off);
    if ((tid & 31) == 0) warpsum[tid >> 5] = cnt;
    __syncthreads();
    if (tid == 0) {
        int tot = 0;
        #pragma unroll
        for (int k = 0; k < 14; k++) tot += warpsum[k];
        atomicAdd(&g_cnt, tot);
        __threadfence();
        int ticket = atomicAdd(&g_done, 1);
        if (ticket == 8 * BATCH - 1) {
            int total = atomicAdd(&g_cnt, 0);
            out[0] = (float)total / 4194304.0f;  // 16*512*512
        }
    }
}

extern "C" void kernel_launch(void* const* d_in, const int* in_sizes, int n_in,
                              void* d_out, int out_size) {
    const float* y_hat = (const float*)d_in[0];
    const float* y     = (const float*)d_in[1];
    float* out = (float*)d_out;

    dim3 g1(WW / TILE, HH / TILE, 2 * BATCH);   // 8 x 8 x 32
    canny_state_kernel<<<g1, NT>>>(y_hat, y);
    dim3 g2(HH / TILE, BATCH);                  // 8 x 16 strips
    hyst_count_kernel<<<g2, 448>>>(out);
}